// round 9
// baseline (speedup 1.0000x reference)
#include <cuda_runtime.h>
#include <cstdint>
#include <math.h>

#define T_SEQ   4096
#define NNODES  64
#define FPL     8
#define OBS_DIM 512
#define HID     64
#define GATES   256
#define FULLMASK 0xffffffffu

// scratch (static device allocations — allowed)
__device__ float g_hs[T_SEQ * NNODES * HID];   // 64 MB: h[t][n][k]
__device__ float g_Wg_t[HID * GATES];
__device__ float g_Wm_t[GATES * HID];
__device__ float g_Ws_t[GATES * HID];

typedef unsigned long long ull;
typedef unsigned int u32;

__device__ __forceinline__ void ffma2(ull& d, const ull a, const ull b) {
    asm("fma.rn.f32x2 %0, %1, %2, %0;" : "+l"(d) : "l"(a), "l"(b));
}
__device__ __forceinline__ ull addf2(ull a, ull b) {
    ull r; asm("add.rn.f32x2 %0, %1, %2;" : "=l"(r) : "l"(a), "l"(b)); return r;
}
__device__ __forceinline__ float2 unpack2(ull v) {
    float2 f; asm("mov.b64 {%0, %1}, %2;" : "=f"(f.x), "=f"(f.y) : "l"(v)); return f;
}
__device__ __forceinline__ ull pack2(float lo, float hi) {
    ull v; asm("mov.b64 %0, {%1, %2};" : "=l"(v) : "f"(lo), "f"(hi)); return v;
}
__device__ __forceinline__ float tanh_mufu(float x) {
    float r; asm("tanh.approx.f32 %0, %1;" : "=f"(r) : "f"(x)); return r;
}
__device__ __forceinline__ u32 smem_u32(const void* p) {
    u32 a;
    asm("{ .reg .u64 t; cvta.to.shared.u64 t, %1; cvt.u32.u64 %0, t; }"
        : "=r"(a) : "l"(p));
    return a;
}

// ---------------------------------------------------------------------------
// Kernel A: one-time weight transposes for head GEMVs
// ---------------------------------------------------------------------------
__global__ void transpose_kernel(const float* __restrict__ Wg,
                                 const float* __restrict__ Wm,
                                 const float* __restrict__ Ws)
{
    int i = blockIdx.x * 256 + threadIdx.x;
    if (i < GATES * HID) {
        int j = i >> 6, k = i & 63;
        g_Wg_t[k * GATES + j] = Wg[i];
        int a = i >> 8, jj = i & 255;
        g_Wm_t[jj * HID + a] = Wm[i];
        g_Ws_t[jj * HID + a] = Ws[i];
    }
}

// ---------------------------------------------------------------------------
// Kernel B: LSTMs. 32 CTAs x 256 threads = 2 INDEPENDENT 128-thread groups,
// one node each, synced only by their own named barrier (bar.sync g+1, 128).
// Each SMSP holds one warp of each group: group A's barrier/chain stalls are
// filled by group B's FFMA work (and vice versa) — first true latency hiding.
// Within a group: thread (k = wg_tid>>1, half = wg_tid&1) computes rows
// gate = 2*half and 2*half+1 for column k, SHARING one h-load per step.
// Gate gather: one shfl.xor(1) pair-exchange + 4 SELs (branch-free).
// Activation via MUFU.TANH with pre-scaled weights. Predicated stores.
// ---------------------------------------------------------------------------
__global__ void __launch_bounds__(256, 1)
lstm_kernel(const float* __restrict__ x,
            const float* __restrict__ W_ih,
            const float* __restrict__ W_hh,
            const float* __restrict__ b_ih,
            const float* __restrict__ b_hh,
            float* __restrict__ out)
{
    const int tid    = threadIdx.x;
    const int grp    = tid >> 7;               // 0 or 1
    const int n      = blockIdx.x * 2 + grp;
    const int wg_tid = tid & 127;
    const int k      = wg_tid >> 1;
    const int half   = wg_tid & 1;
    const int gate0  = 2 * half;               // 0 (i) or 2 (g)
    const int gate1  = 2 * half + 1;           // 1 (f) or 3 (o)
    const int r0     = gate0 * HID + k;
    const int r1     = gate1 * HID + k;

    // row scales: sigmoid rows use 0.5 (sigma(z)=0.5+0.5*tanh(z/2)), tanh row 1
    const float m0 = (gate0 == 2) ? 1.0f : 0.5f;
    const float A0 = m0, B0 = (gate0 == 2) ? 0.0f : 0.5f;
    const float m1 = 0.5f;                     // gates 1,3 are both sigmoid
    const float A1 = 0.5f, B1 = 0.5f;

    __shared__ __align__(16) float h2[2][2][HID];        // [grp][parity][k]
    __shared__ __align__(16) float xs[2][2][32][FPL];    // [grp][buf][s][j]

    // weights in registers, pre-scaled, packed f32x2
    ull whh0[32], whh1[32];
    {
        const float* w0 = W_hh + r0 * HID;
        const float* w1 = W_hh + r1 * HID;
#pragma unroll
        for (int i = 0; i < 32; i++) {
            whh0[i] = pack2(w0[2*i] * m0, w0[2*i+1] * m0);
            whh1[i] = pack2(w1[2*i] * m1, w1[2*i+1] * m1);
        }
    }
    ull wih0[4], wih1[4];
    {
        const float* w0 = W_ih + r0 * FPL;
        const float* w1 = W_ih + r1 * FPL;
#pragma unroll
        for (int i = 0; i < 4; i++) {
            wih0[i] = pack2(w0[2*i] * m0, w0[2*i+1] * m0);
            wih1[i] = pack2(w1[2*i] * m1, w1[2*i+1] * m1);
        }
    }
    const float bs0 = (b_ih[r0] + b_hh[r0]) * m0;
    const float bs1 = (b_ih[r1] + b_hh[r1]) * m1;

    const u32 h2_base = smem_u32(h2);   // base of h2[0][0][0]
    float c_reg = 0.0f;
    if (wg_tid < HID) h2[grp][0][wg_tid] = 0.0f;

    // prologue: stage x batch 0 for this group's node (2 floats/thread)
    {
        int i0 = wg_tid, i1 = wg_tid + 128;
        xs[grp][0][i0 >> 3][i0 & 7] = x[(i0 >> 3) * OBS_DIM + n * FPL + (i0 & 7)];
        xs[grp][0][i1 >> 3][i1 & 7] = x[(i1 >> 3) * OBS_DIM + n * FPL + (i1 & 7)];
    }
    __syncthreads();   // one-time joint start

    const float* hs_ptr = g_hs + n * HID + k;
    const int barid = grp + 1;

    for (int b = 0; b < T_SEQ / 32; b++) {
        // prefetch next x batch into registers
        float xpA = 0.0f, xpB = 0.0f;
        {
            int i0 = wg_tid, i1 = wg_tid + 128;
            int t0 = (b + 1) * 32 + (i0 >> 3);
            int t1 = (b + 1) * 32 + (i1 >> 3);
            if (t0 < T_SEQ) xpA = x[t0 * OBS_DIM + n * FPL + (i0 & 7)];
            if (t1 < T_SEQ) xpB = x[t1 * OBS_DIM + n * FPL + (i1 & 7)];
        }
#pragma unroll 2
        for (int s = 0; s < 32; s++) {
            const int par = s & 1;

            // two row-dots sharing one h read
            ull a0 = pack2(bs0, 0.0f), a1 = 0, a2 = 0, a3 = 0;
            ull e0 = pack2(bs1, 0.0f), e1 = 0, e2 = 0, e3 = 0;
            {
                const ulonglong2* xp = (const ulonglong2*)xs[grp][b & 1][s];
                ulonglong2 xv0 = xp[0], xv1 = xp[1];
                ffma2(a0, wih0[0], xv0.x); ffma2(e0, wih1[0], xv0.x);
                ffma2(a1, wih0[1], xv0.y); ffma2(e1, wih1[1], xv0.y);
                ffma2(a2, wih0[2], xv1.x); ffma2(e2, wih1[2], xv1.x);
                ffma2(a3, wih0[3], xv1.y); ffma2(e3, wih1[3], xv1.y);
            }
            const ulonglong2* hp = (const ulonglong2*)h2[grp][par];
#pragma unroll
            for (int mm = 0; mm < 4; mm++) {
                ulonglong2 hv0 = hp[4*mm + 0], hv1 = hp[4*mm + 1];
                ulonglong2 hv2 = hp[4*mm + 2], hv3 = hp[4*mm + 3];
                ffma2(a0, whh0[8*mm+0], hv0.x); ffma2(e0, whh1[8*mm+0], hv0.x);
                ffma2(a1, whh0[8*mm+1], hv0.y); ffma2(e1, whh1[8*mm+1], hv0.y);
                ffma2(a2, whh0[8*mm+2], hv1.x); ffma2(e2, whh1[8*mm+2], hv1.x);
                ffma2(a3, whh0[8*mm+3], hv1.y); ffma2(e3, whh1[8*mm+3], hv1.y);
                ffma2(a0, whh0[8*mm+4], hv2.x); ffma2(e0, whh1[8*mm+4], hv2.x);
                ffma2(a1, whh0[8*mm+5], hv2.y); ffma2(e1, whh1[8*mm+5], hv2.y);
                ffma2(a2, whh0[8*mm+6], hv3.x); ffma2(e2, whh1[8*mm+6], hv3.x);
                ffma2(a3, whh0[8*mm+7], hv3.y); ffma2(e3, whh1[8*mm+7], hv3.y);
            }
            float2 fA = unpack2(addf2(addf2(a0, a1), addf2(a2, a3)));
            float2 fB = unpack2(addf2(addf2(e0, e1), addf2(e2, e3)));
            const float z0 = fA.x + fA.y;
            const float z1 = fB.x + fB.y;

            // activations (branch-free)
            const float v0 = fmaf(tanh_mufu(z0), A0, B0);
            const float v1 = fmaf(tanh_mufu(z1), A1, B1);

            // pair exchange with lane^1 (partner holds the other 2 gates)
            const float p0 = __shfl_xor_sync(FULLMASK, v0, 1);
            const float p1 = __shfl_xor_sync(FULLMASK, v1, 1);

            // branch-free gate select (SELs):
            // even lane (half=0): i=v0 f=v1 g=p0 o=p1 ; odd: i=p0 f=p1 g=v0 o=v1
            const float vi = half ? p0 : v0;
            const float vf = half ? p1 : v1;
            const float vg = half ? v0 : p0;
            const float vo = half ? v1 : p1;

            // c/h computed in both lanes of the pair (identical)
            c_reg = vf * c_reg + vi * vg;
            const float h = vo * tanh_mufu(c_reg);

            // predicated stores: even (half==0) lanes commit
            {
                const u32 sts_addr = h2_base +
                    (u32)(((grp * 2 + (par ^ 1)) * HID + k) * 4);
                asm volatile(
                    "{ .reg .pred p; setp.eq.s32 p, %0, 0;\n\t"
                    "@p st.shared.f32 [%1], %3;\n\t"
                    "@p st.global.f32 [%2], %3; }"
                    :: "r"(half), "r"(sts_addr), "l"(hs_ptr), "f"(h)
                    : "memory");
            }
            hs_ptr += NNODES * HID;

            // stage next x batch mid-way (write-only buffer this batch)
            if (s == 20) {
                int i0 = wg_tid, i1 = wg_tid + 128;
                xs[grp][(b + 1) & 1][i0 >> 3][i0 & 7] = xpA;
                xs[grp][(b + 1) & 1][i1 >> 3][i1 & 7] = xpB;
            }
            // group-local named barrier (128 threads)
            asm volatile("bar.sync %0, 128;" :: "r"(barid) : "memory");
        }
    }

    // hn / cn (t=4095 wrote parity 0)
    if (half == 0) {
        const int base = 2 * T_SEQ * NNODES;
        out[base + n * HID + k] = h2[grp][0][k];
        out[base + NNODES * HID + n * HID + k] = c_reg;
    }
}

// ---------------------------------------------------------------------------
// Kernel C: warp-autonomous head. 512 CTAs x 8 warps; one warp per timestep.
// GAT collapses to identity-attention; mean-pool commutes with W_gat.
// ---------------------------------------------------------------------------
__global__ void __launch_bounds__(256, 2)
head_kernel(const float* __restrict__ b_gat,
            const float* __restrict__ b_mean,
            const float* __restrict__ b_std,
            float* __restrict__ out)
{
    const int w    = threadIdx.x >> 5;
    const int lane = threadIdx.x & 31;
    const int t    = blockIdx.x * 8 + w;

    __shared__ __align__(16) float hb[8][HID];
    __shared__ __align__(16) float gs[8][GATES];

    {
        const float* p = g_hs + (long)t * (NNODES * HID);
        float s0 = 0.0f, s1 = 0.0f;
#pragma unroll 8
        for (int n = 0; n < NNODES; n++) {
            s0 += p[n * HID + lane];
            s1 += p[n * HID + 32 + lane];
        }
        hb[w][lane]      = s0 * (1.0f / 64.0f);
        hb[w][32 + lane] = s1 * (1.0f / 64.0f);
    }
    __syncwarp();

#pragma unroll
    for (int i = 0; i < 8; i++) {
        const int j = i * 32 + lane;
        float acc = b_gat[j];
#pragma unroll 8
        for (int k = 0; k < HID; k++)
            acc += g_Wg_t[k * GATES + j] * hb[w][k];
        gs[w][j] = fmaxf(acc, 0.0f);
    }
    __syncwarp();

#pragma unroll
    for (int i = 0; i < 2; i++) {
        const int a = i * 32 + lane;
        float am = b_mean[a], as = b_std[a];
#pragma unroll 8
        for (int j = 0; j < GATES; j++) {
            const float gv = gs[w][j];
            am += g_Wm_t[j * HID + a] * gv;
            as += g_Ws_t[j * HID + a] * gv;
        }
        out[t * NNODES + a] = am;
        float sp = (as > 20.0f) ? as : log1pf(__expf(as));
        out[T_SEQ * NNODES + t * NNODES + a] = fminf(fmaxf(sp, 0.001f), 10.0f);
    }
}

// ---------------------------------------------------------------------------
// launch
// ---------------------------------------------------------------------------
extern "C" void kernel_launch(void* const* d_in, const int* in_sizes, int n_in,
                              void* d_out, int out_size)
{
    const float* x      = (const float*)d_in[0];
    const float* W_ih   = (const float*)d_in[1];
    const float* W_hh   = (const float*)d_in[2];
    const float* b_ih   = (const float*)d_in[3];
    const float* b_hh   = (const float*)d_in[4];
    const float* W_gat  = (const float*)d_in[5];
    // d_in[6], d_in[7] (att_src/att_dst) provably unused: identity adjacency
    // -> softmax over a single unmasked element == 1 for any logits.
    const float* b_gat  = (const float*)d_in[8];
    const float* b_mean = (const float*)d_in[10];
    const float* b_std  = (const float*)d_in[12];
    float* out = (float*)d_out;

    transpose_kernel<<<64, 256>>>(W_gat, (const float*)d_in[9], (const float*)d_in[11]);
    lstm_kernel<<<NNODES / 2, 256>>>(x, W_ih, W_hh, b_ih, b_hh, out);
    head_kernel<<<T_SEQ / 8, 256>>>(b_gat, b_mean, b_std, out);
}